// round 2
// baseline (speedup 1.0000x reference)
#include <cuda_runtime.h>
#include <math.h>

#define D 128
#define NMAX 100000

// -------- device scratch (allocation-free: __device__ globals) --------
__device__ float g_pA[(size_t)NMAX * D];   // softmax(logits_A)
__device__ float g_pB[(size_t)NMAX * D];   // softmax(logits_B)
__device__ float g_SAB[(size_t)NMAX * D];  // segment_sum over AB edges (dst in B)
__device__ float g_SBA[(size_t)NMAX * D];  // segment_sum over BA edges (dst in A)
__device__ float g_SAA[(size_t)NMAX * D];  // segment_sum over AA edges (dst in A)

// -------- helpers --------
__device__ __forceinline__ float softplusf(float x) {
    // numerically stable softplus
    return fmaxf(x, 0.0f) + log1pf(__expf(-fabsf(x)));
}

__device__ __forceinline__ void red_add_v4(float* addr, float4 v) {
    asm volatile("red.global.add.v4.f32 [%0], {%1, %2, %3, %4};"
                 :: "l"(addr), "f"(v.x), "f"(v.y), "f"(v.z), "f"(v.w)
                 : "memory");
}

// -------- kernel 1: fused softmax for both node sets (one warp per row) --------
__global__ void softmax_kernel(const float* __restrict__ A,
                               const float* __restrict__ B,
                               int nA, int nTot) {
    int gw   = (blockIdx.x * blockDim.x + threadIdx.x) >> 5;
    int lane = threadIdx.x & 31;
    if (gw >= nTot) return;

    const float* src;
    float* dst;
    if (gw < nA) { src = A + (size_t)gw * D;        dst = g_pA + (size_t)gw * D; }
    else         { src = B + (size_t)(gw - nA) * D; dst = g_pB + (size_t)(gw - nA) * D; }

    float4 v = ((const float4*)src)[lane];
    float m = fmaxf(fmaxf(v.x, v.y), fmaxf(v.z, v.w));
    #pragma unroll
    for (int o = 16; o; o >>= 1) m = fmaxf(m, __shfl_xor_sync(0xffffffffu, m, o));

    float4 e;
    e.x = __expf(v.x - m); e.y = __expf(v.y - m);
    e.z = __expf(v.z - m); e.w = __expf(v.w - m);
    float s = e.x + e.y + e.z + e.w;
    #pragma unroll
    for (int o = 16; o; o >>= 1) s += __shfl_xor_sync(0xffffffffu, s, o);

    float inv = __frcp_rn(s);
    e.x *= inv; e.y *= inv; e.z *= inv; e.w *= inv;
    ((float4*)dst)[lane] = e;
}

// -------- kernel 2: zero the three accumulators --------
__global__ void zero_kernel(int nA32, int nB32) {
    int i = blockIdx.x * blockDim.x + threadIdx.x;
    int stride = gridDim.x * blockDim.x;
    float4 z = make_float4(0.f, 0.f, 0.f, 0.f);
    for (int j = i; j < nB32; j += stride) ((float4*)g_SAB)[j] = z;
    for (int j = i; j < nA32; j += stride) {
        ((float4*)g_SBA)[j] = z;
        ((float4*)g_SAA)[j] = z;
    }
}

// -------- kernel 3: edge scatter (one warp per edge, vectorized RED) --------
__device__ __forceinline__ void scatter_impl(const float* __restrict__ p,
                                             const int* __restrict__ e, int E,
                                             float* __restrict__ S) {
    int gw   = (blockIdx.x * blockDim.x + threadIdx.x) >> 5;
    int lane = threadIdx.x & 31;
    if (gw >= E) return;
    int src = e[gw];
    int dst = e[E + gw];
    float4 v = ((const float4*)(p + (size_t)src * D))[lane];
    red_add_v4(S + (size_t)dst * D + (lane << 2), v);
}

__global__ void scatterAB_kernel(const int* __restrict__ e, int E) { scatter_impl(g_pA, e, E, g_SAB); }
__global__ void scatterBA_kernel(const int* __restrict__ e, int E) { scatter_impl(g_pB, e, E, g_SBA); }
__global__ void scatterAA_kernel(const int* __restrict__ e, int E) { scatter_impl(g_pA, e, E, g_SAA); }

// -------- kernel 4: out[M,128] = sum_p S_p[M,128] @ (Wpos_p - softplus(Wneg_p)) --------
__device__ __forceinline__ const float* sel_S(int s) {
    switch (s) {
        case 0: return g_SAB;
        case 1: return g_SBA;
        default: return g_SAA;
    }
}

template<int NPAIRS>
__global__ void __launch_bounds__(256)
gemm_kernel(int sel0, const float* __restrict__ Wp0, const float* __restrict__ Wn0,
            int sel1, const float* __restrict__ Wp1, const float* __restrict__ Wn1,
            float* __restrict__ out, int M) {
    extern __shared__ float sm[];
    float* Wsm = sm;                    // NPAIRS * 128*128
    float* Ssm = sm + NPAIRS * D * D;   // 64 * 128

    const float* Sg[2];
    Sg[0] = sel_S(sel0);
    if (NPAIRS == 2) Sg[1] = sel_S(sel1);

    // Load W(s) once per block, fusing the softplus transform.
    #pragma unroll
    for (int p = 0; p < NPAIRS; ++p) {
        const float4* wp = (const float4*)(p == 0 ? Wp0 : Wp1);
        const float4* wn = (const float4*)(p == 0 ? Wn0 : Wn1);
        float4* wd = (float4*)(Wsm + p * D * D);
        for (int i = threadIdx.x; i < D * D / 4; i += 256) {
            float4 a = wp[i], b = wn[i];
            wd[i] = make_float4(a.x - softplusf(b.x), a.y - softplusf(b.y),
                                a.z - softplusf(b.z), a.w - softplusf(b.w));
        }
    }

    int c4 = (threadIdx.x & 31) << 2;   // 4-column strip
    int r0 = threadIdx.x >> 5;          // row group 0..7

    int tiles = (M + 63) >> 6;
    for (int t = blockIdx.x; t < tiles; t += gridDim.x) {
        int base = t << 6;
        int rows = min(64, M - base);
        float acc[8][4] = {};

        #pragma unroll
        for (int p = 0; p < NPAIRS; ++p) {
            __syncthreads();  // protect Ssm (covers W load on first pass + prior-tile reads)
            const float4* src = (const float4*)(Sg[p] + (size_t)base * D);
            for (int i = threadIdx.x; i < rows * 32; i += 256)
                ((float4*)Ssm)[i] = src[i];
            __syncthreads();

            const float* W = Wsm + p * D * D;
            #pragma unroll 4
            for (int k = 0; k < D; ++k) {
                float4 w = *(const float4*)(W + k * D + c4);
                #pragma unroll
                for (int j = 0; j < 8; ++j) {
                    float s = Ssm[((r0 + (j << 3)) << 7) + k];
                    acc[j][0] = fmaf(s, w.x, acc[j][0]);
                    acc[j][1] = fmaf(s, w.y, acc[j][1]);
                    acc[j][2] = fmaf(s, w.z, acc[j][2]);
                    acc[j][3] = fmaf(s, w.w, acc[j][3]);
                }
            }
        }

        #pragma unroll
        for (int j = 0; j < 8; ++j) {
            int r = base + r0 + (j << 3);
            if (r < M)
                *(float4*)(out + (size_t)r * D + c4) =
                    make_float4(acc[j][0], acc[j][1], acc[j][2], acc[j][3]);
        }
    }
}

// -------- launch --------
extern "C" void kernel_launch(void* const* d_in, const int* in_sizes, int n_in,
                              void* d_out, int out_size) {
    const float* logits_A = (const float*)d_in[0];
    const float* logits_B = (const float*)d_in[1];
    // d_in[2], d_in[3]: frozen_A / frozen_B — do not affect the math
    const int* eAB = (const int*)d_in[4];
    const int* eBA = (const int*)d_in[5];
    const int* eAA = (const int*)d_in[6];
    const float* WpAB = (const float*)d_in[7];
    const float* WnAB = (const float*)d_in[8];
    const float* WpBA = (const float*)d_in[9];
    const float* WnBA = (const float*)d_in[10];
    const float* WpAA = (const float*)d_in[11];
    const float* WnAA = (const float*)d_in[12];

    int nA = in_sizes[0] / D;
    int nB = in_sizes[1] / D;
    int EAB = in_sizes[4] / 2;
    int EBA = in_sizes[5] / 2;
    int EAA = in_sizes[6] / 2;

    float* outA = (float*)d_out;                  // delta_A first
    float* outB = outA + (size_t)nA * D;          // then delta_B

    // 1) softmax over both node sets
    int rows = nA + nB;
    softmax_kernel<<<(rows + 7) / 8, 256>>>(logits_A, logits_B, nA, rows);

    // 2) zero accumulators
    zero_kernel<<<1024, 256>>>(nA * 32, nB * 32);

    // 3) edge scatters (one warp per edge)
    if (EAB > 0) scatterAB_kernel<<<(EAB + 7) / 8, 256>>>(eAB, EAB);
    if (EBA > 0) scatterBA_kernel<<<(EBA + 7) / 8, 256>>>(eBA, EBA);
    if (EAA > 0) scatterAA_kernel<<<(EAA + 7) / 8, 256>>>(eAA, EAA);

    // 4) GEMMs
    size_t smem1 = (size_t)(1 * D * D + 64 * D) * sizeof(float);  //  96 KB
    size_t smem2 = (size_t)(2 * D * D + 64 * D) * sizeof(float);  // 160 KB
    cudaFuncSetAttribute(gemm_kernel<1>, cudaFuncAttributeMaxDynamicSharedMemorySize, (int)smem1);
    cudaFuncSetAttribute(gemm_kernel<2>, cudaFuncAttributeMaxDynamicSharedMemorySize, (int)smem2);

    // delta_B = S_AB @ W_AB
    gemm_kernel<1><<<592, 256, smem1>>>(0, WpAB, WnAB, 0, nullptr, nullptr, outB, nB);
    // delta_A = S_BA @ W_BA + S_AA @ W_AA
    gemm_kernel<2><<<296, 256, smem2>>>(1, WpBA, WnBA, 2, WpAA, WnAA, outA, nA);
}

// round 7
// speedup vs baseline: 1.2618x; 1.2618x over previous
#include <cuda_runtime.h>
#include <cuda_bf16.h>
#include <math.h>
#include <stdint.h>

#define D 128
#define NMAX 100000

// -------- device scratch (allocation-free: __device__ globals) --------
__device__ float g_pA[(size_t)NMAX * D];   // softmax(logits_A)
__device__ float g_pB[(size_t)NMAX * D];   // softmax(logits_B)
__device__ float g_SAB[(size_t)NMAX * D];  // segment_sum over AB edges (dst in B)
__device__ float g_SBA[(size_t)NMAX * D];  // segment_sum over BA edges (dst in A)
__device__ float g_SAA[(size_t)NMAX * D];  // segment_sum over AA edges (dst in A)
// W^T (softplus-transformed), hi/lo bf16 split, plain [n][k] row-major.
// 0:AB_hi 1:AB_lo 2:BA_hi 3:BA_lo 4:AA_hi 5:AA_lo  (each 128x128 bf16)
__device__ __nv_bfloat16 g_Wt[6 * 128 * 128];

// -------- helpers --------
__device__ __forceinline__ float softplusf(float x) {
    return fmaxf(x, 0.0f) + log1pf(__expf(-fabsf(x)));
}
__device__ __forceinline__ void red_add_v4(float* addr, float4 v) {
    asm volatile("red.global.add.v4.f32 [%0], {%1, %2, %3, %4};"
                 :: "l"(addr), "f"(v.x), "f"(v.y), "f"(v.z), "f"(v.w)
                 : "memory");
}
__device__ __forceinline__ uint32_t s2u(const void* p) {
    uint32_t a;
    asm("{ .reg .u64 t; cvta.to.shared.u64 t, %1; cvt.u32.u64 %0, t; }"
        : "=r"(a) : "l"(p));
    return a;
}
__device__ __forceinline__ void ldsm_x4(uint32_t& r0, uint32_t& r1, uint32_t& r2,
                                        uint32_t& r3, uint32_t a) {
    asm volatile("ldmatrix.sync.aligned.m8n8.x4.shared.b16 {%0,%1,%2,%3}, [%4];"
                 : "=r"(r0), "=r"(r1), "=r"(r2), "=r"(r3) : "r"(a));
}
__device__ __forceinline__ void ldsm_x2(uint32_t& r0, uint32_t& r1, uint32_t a) {
    asm volatile("ldmatrix.sync.aligned.m8n8.x2.shared.b16 {%0,%1}, [%2];"
                 : "=r"(r0), "=r"(r1) : "r"(a));
}
__device__ __forceinline__ void mma16816(float* c, const uint32_t* A, const uint32_t* B) {
    asm volatile(
        "mma.sync.aligned.m16n8k16.row.col.f32.bf16.bf16.f32 "
        "{%0,%1,%2,%3}, {%4,%5,%6,%7}, {%8,%9}, {%0,%1,%2,%3};"
        : "+f"(c[0]), "+f"(c[1]), "+f"(c[2]), "+f"(c[3])
        : "r"(A[0]), "r"(A[1]), "r"(A[2]), "r"(A[3]), "r"(B[0]), "r"(B[1]));
}

// -------- kernel 1: fused softmax (one warp per row) --------
__global__ void softmax_kernel(const float* __restrict__ A,
                               const float* __restrict__ B,
                               int nA, int nTot) {
    int gw   = (blockIdx.x * blockDim.x + threadIdx.x) >> 5;
    int lane = threadIdx.x & 31;
    if (gw >= nTot) return;
    const float* src;
    float* dst;
    if (gw < nA) { src = A + (size_t)gw * D;        dst = g_pA + (size_t)gw * D; }
    else         { src = B + (size_t)(gw - nA) * D; dst = g_pB + (size_t)(gw - nA) * D; }
    float4 v = ((const float4*)src)[lane];
    float m = fmaxf(fmaxf(v.x, v.y), fmaxf(v.z, v.w));
    #pragma unroll
    for (int o = 16; o; o >>= 1) m = fmaxf(m, __shfl_xor_sync(0xffffffffu, m, o));
    float4 e;
    e.x = __expf(v.x - m); e.y = __expf(v.y - m);
    e.z = __expf(v.z - m); e.w = __expf(v.w - m);
    float s = e.x + e.y + e.z + e.w;
    #pragma unroll
    for (int o = 16; o; o >>= 1) s += __shfl_xor_sync(0xffffffffu, s, o);
    float inv = __frcp_rn(s);
    e.x *= inv; e.y *= inv; e.z *= inv; e.w *= inv;
    ((float4*)dst)[lane] = e;
}

// -------- kernel 2: zero accumulators --------
__global__ void zero_kernel(int nA32, int nB32) {
    int i = blockIdx.x * blockDim.x + threadIdx.x;
    int stride = gridDim.x * blockDim.x;
    float4 z = make_float4(0.f, 0.f, 0.f, 0.f);
    for (int j = i; j < nB32; j += stride) ((float4*)g_SAB)[j] = z;
    for (int j = i; j < nA32; j += stride) {
        ((float4*)g_SBA)[j] = z;
        ((float4*)g_SAA)[j] = z;
    }
}

// -------- kernel 3: W prep — transpose + softplus + hi/lo split --------
__global__ void prep_w_kernel(const float* __restrict__ Wp0, const float* __restrict__ Wn0,
                              const float* __restrict__ Wp1, const float* __restrict__ Wn1,
                              const float* __restrict__ Wp2, const float* __restrict__ Wn2) {
    int w = blockIdx.x;  // 0=AB, 1=BA, 2=AA
    const float* Wp = (w == 0) ? Wp0 : (w == 1) ? Wp1 : Wp2;
    const float* Wn = (w == 0) ? Wn0 : (w == 1) ? Wn1 : Wn2;
    __nv_bfloat16* hi = g_Wt + (size_t)(2 * w) * D * D;
    __nv_bfloat16* lo = g_Wt + (size_t)(2 * w + 1) * D * D;
    for (int idx = threadIdx.x; idx < D * D; idx += blockDim.x) {
        int n = idx & 127;       // dest row (N)
        int k = idx >> 7;        // dest col (K)
        float x = Wp[k * D + n] - softplusf(Wn[k * D + n]);
        __nv_bfloat16 h = __float2bfloat16(x);
        __nv_bfloat16 l = __float2bfloat16(x - __bfloat162float(h));
        hi[n * D + k] = h;       // [n][k] row-major, k contiguous
        lo[n * D + k] = l;
    }
}

// -------- kernel 4: fused edge scatter (one warp per edge) --------
__global__ void scatter_all_kernel(const int* __restrict__ eAB,
                                   const int* __restrict__ eBA,
                                   const int* __restrict__ eAA,
                                   int EAB, int EBA, int EAA) {
    int gw   = (blockIdx.x * blockDim.x + threadIdx.x) >> 5;
    int lane = threadIdx.x & 31;
    const float* p;
    float* S;
    const int* e;
    int E, i;
    if (gw < EAB)               { p = g_pA; S = g_SAB; e = eAB; E = EAB; i = gw; }
    else if ((gw -= EAB) < EBA) { p = g_pB; S = g_SBA; e = eBA; E = EBA; i = gw; }
    else if ((gw -= EBA) < EAA) { p = g_pA; S = g_SAA; e = eAA; E = EAA; i = gw; }
    else return;
    int src = e[i];
    int dst = e[E + i];
    float4 v = ((const float4*)(p + (size_t)src * D))[lane];
    red_add_v4(S + (size_t)dst * D + (lane << 2), v);
}

// -------- kernel 5: mma.sync bf16x3 GEMM --------
__device__ __forceinline__ const float* sel_S(int s) {
    switch (s) {
        case 0: return g_SAB;
        case 1: return g_SBA;
        default: return g_SAA;
    }
}

// SMEM layout: padded rows, stride 272B (128 bf16 + 16B pad -> conflict-free LDSM)
#define RSTRIDE 272
#define SM_AHI 0
#define SM_ALO (SM_AHI + 128 * RSTRIDE)   // 34816
#define SM_BHI (SM_ALO + 128 * RSTRIDE)   // 69632
#define SM_BLO (SM_BHI + 128 * RSTRIDE)   // 104448
#define SM_TOT (SM_BLO + 128 * RSTRIDE)   // 139264

template<int NPAIRS>
__global__ void __launch_bounds__(256, 1)
gemm_mma(int sel0, int sel1, int wbuf0, int wbuf1, float* __restrict__ out, int M) {
    extern __shared__ char sm[];
    uint32_t sb = s2u(sm);
    int tid = threadIdx.x, w = tid >> 5, lane = tid & 31;
    int mw = (w & 3) << 5;   // warp m offset (0/32/64/96)
    int nw = (w >> 2) << 6;  // warp n offset (0/64)
    int base = blockIdx.x << 7;

    float acc[2][8][4];
    #pragma unroll
    for (int a = 0; a < 2; ++a)
        #pragma unroll
        for (int b = 0; b < 8; ++b)
            #pragma unroll
            for (int c = 0; c < 4; ++c) acc[a][b][c] = 0.f;

    // ldmatrix lane addresses (byte offsets inside a tile buffer)
    // A x4: matrix = lane>>3: row = (lane&7) + ((lane>>3)&1)*8, koff = (lane>>4)*8
    int a_row = (lane & 7) + ((lane >> 3) & 1) * 8;
    int a_koff = (lane >> 4) * 8;
    // B x2: lanes 0-15: row n = lane&7, koff = (lane>>3)*8
    int b_row = lane & 7;
    int b_koff = ((lane >> 3) & 1) * 8;

    #pragma unroll
    for (int p = 0; p < NPAIRS; ++p) {
        if (p > 0) __syncthreads();  // protect smem reuse across pairs

        // copy W pair (hi/lo) into padded smem: 128 rows x 8 float4-chunks
        {
            const float4* gh = (const float4*)(g_Wt + (size_t)(p == 0 ? wbuf0 : wbuf1) * D * D);
            const float4* gl = gh + (D * D / 8);
            for (int i = tid; i < 128 * 16; i += 256) {
                int r = i >> 4, c = i & 15;
                *(float4*)(sm + SM_BHI + r * RSTRIDE + c * 16) = gh[r * 16 + c];
                *(float4*)(sm + SM_BLO + r * RSTRIDE + c * 16) = gl[r * 16 + c];
            }
        }
        // load + convert A tile (fp32 -> bf16 hi/lo), zero-padded past M
        {
            const float* Sg = sel_S(p == 0 ? sel0 : sel1);
            #pragma unroll 4
            for (int j = 0; j < 16; ++j) {
                int i = tid + j * 256;           // float4 index
                int row = i >> 5, q = i & 31;
                int grow = base + row;
                float4 v = make_float4(0.f, 0.f, 0.f, 0.f);
                if (grow < M) v = ((const float4*)(Sg + (size_t)grow * D))[q];
                __nv_bfloat16 h0 = __float2bfloat16(v.x), h1 = __float2bfloat16(v.y);
                __nv_bfloat16 h2 = __float2bfloat16(v.z), h3 = __float2bfloat16(v.w);
                __nv_bfloat162 hA; hA.x = h0; hA.y = h1;
                __nv_bfloat162 hB; hB.x = h2; hB.y = h3;
                __nv_bfloat162 lA, lB;
                lA.x = __float2bfloat16(v.x - __bfloat162float(h0));
                lA.y = __float2bfloat16(v.y - __bfloat162float(h1));
                lB.x = __float2bfloat16(v.z - __bfloat162float(h2));
                lB.y = __float2bfloat16(v.w - __bfloat162float(h3));
                char* ph = sm + SM_AHI + row * RSTRIDE + q * 8;
                char* pl = sm + SM_ALO + row * RSTRIDE + q * 8;
                *(__nv_bfloat162*)ph = hA; *(__nv_bfloat162*)(ph + 4) = hB;
                *(__nv_bfloat162*)pl = lA; *(__nv_bfloat162*)(pl + 4) = lB;
            }
        }
        __syncthreads();

        #pragma unroll
        for (int ks = 0; ks < 8; ++ks) {
            int k0 = ks << 4;
            uint32_t Ahi[2][4], Alo[2][4], Bhi[8][2], Blo[8][2];
            #pragma unroll
            for (int m2 = 0; m2 < 2; ++m2) {
                uint32_t ao = (uint32_t)((mw + (m2 << 4) + a_row) * RSTRIDE
                                          + (k0 + a_koff) * 2);
                ldsm_x4(Ahi[m2][0], Ahi[m2][1], Ahi[m2][2], Ahi[m2][3], sb + SM_AHI + ao);
                ldsm_x4(Alo[m2][0], Alo[m2][1], Alo[m2][2], Alo[m2][3], sb + SM_ALO + ao);
            }
            #pragma unroll
            for (int j = 0; j < 8; ++j) {
                uint32_t bo = (uint32_t)((nw + (j << 3) + b_row) * RSTRIDE
                                          + (k0 + b_koff) * 2);
                ldsm_x2(Bhi[j][0], Bhi[j][1], sb + SM_BHI + bo);
                ldsm_x2(Blo[j][0], Blo[j][1], sb + SM_BLO + bo);
            }
            #pragma unroll
            for (int m2 = 0; m2 < 2; ++m2)
                #pragma unroll
                for (int j = 0; j < 8; ++j) {
                    mma16816(acc[m2][j], Ahi[m2], Bhi[j]);
                    mma16816(acc[m2][j], Ahi[m2], Blo[j]);
                    mma16816(acc[m2][j], Alo[m2], Bhi[j]);
                }
        }
    }

    // epilogue: fragment (m2, j): rows base+mw+m2*16+gid(+8), cols nw+j*8+2*tig
    int gid = lane >> 2, tig = lane & 3;
    #pragma unroll
    for (int m2 = 0; m2 < 2; ++m2) {
        int r0 = base + mw + (m2 << 4) + gid;
        #pragma unroll
        for (int j = 0; j < 8; ++j) {
            int col = nw + (j << 3) + (tig << 1);
            if (r0 < M)
                *(float2*)(out + (size_t)r0 * D + col) = make_float2(acc[m2][j][0], acc[m2][j][1]);
            if (r0 + 8 < M)
                *(float2*)(out + (size_t)(r0 + 8) * D + col) = make_float2(acc[m2][j][2], acc[m2][j][3]);
        }
    }
}

// -------- launch --------
extern "C" void kernel_launch(void* const* d_in, const int* in_sizes, int n_in,
                              void* d_out, int out_size) {
    const float* logits_A = (const float*)d_in[0];
    const float* logits_B = (const float*)d_in[1];
    const int* eAB = (const int*)d_in[4];
    const int* eBA = (const int*)d_in[5];
    const int* eAA = (const int*)d_in[6];
    const float* WpAB = (const float*)d_in[7];
    const float* WnAB = (const float*)d_in[8];
    const float* WpBA = (const float*)d_in[9];
    const float* WnBA = (const float*)d_in[10];
    const float* WpAA = (const float*)d_in[11];
    const float* WnAA = (const float*)d_in[12];

    int nA = in_sizes[0] / D;
    int nB = in_sizes[1] / D;
    int EAB = in_sizes[4] / 2;
    int EBA = in_sizes[5] / 2;
    int EAA = in_sizes[6] / 2;

    float* outA = (float*)d_out;
    float* outB = outA + (size_t)nA * D;

    // 1) softmax
    int rows = nA + nB;
    softmax_kernel<<<(rows + 7) / 8, 256>>>(logits_A, logits_B, nA, rows);

    // 2) zero accumulators
    zero_kernel<<<1024, 256>>>(nA * 32, nB * 32);

    // 3) W prep
    prep_w_kernel<<<3, 256>>>(WpAB, WnAB, WpBA, WnBA, WpAA, WnAA);

    // 4) fused edge scatter
    int Etot = EAB + EBA + EAA;
    if (Etot > 0)
        scatter_all_kernel<<<(Etot + 7) / 8, 256>>>(eAB, eBA, eAA, EAB, EBA, EAA);

    // 5) tensor-core GEMMs (mma.sync bf16 x3)
    cudaFuncSetAttribute(gemm_mma<1>, cudaFuncAttributeMaxDynamicSharedMemorySize, SM_TOT);
    cudaFuncSetAttribute(gemm_mma<2>, cudaFuncAttributeMaxDynamicSharedMemorySize, SM_TOT);

    int tilesB = (nB + 127) / 128;
    int tilesA = (nA + 127) / 128;
    // delta_B = S_AB @ W_AB
    gemm_mma<1><<<tilesB, 256, SM_TOT>>>(0, 0, 0, 0, outB, nB);
    // delta_A = S_BA @ W_BA + S_AA @ W_AA
    gemm_mma<2><<<tilesA, 256, SM_TOT>>>(1, 2, 2, 4, outA, nA);
}